// round 14
// baseline (speedup 1.0000x reference)
#include <cuda_runtime.h>
#include <cuda_fp16.h>
#include <cstdint>

// ---------------- scratch (static device globals) ---------------------------
// votes layout: [b][n][c(10)][o(16)] halves -> ROW=160 halves per (b,n).
__device__ __half g_votes[256u * 1152u * 160u];  // ~94 MB
__device__ float  g_s0[256 * 160];               // pass-0 s accumulator

// ---------------- constants -------------------------------------------------
#define NB      256
#define NN      1152
#define NC      10
#define CO      160
#define ROW     160            // halves per (b,n) row
#define GN      16             // n's per votes block
#define NGRP    (NN/GN)        // 72
#define HN      576            // n's per CTA in fused route (cluster of 2)
#define POSE_OFF   0
#define ACT_OFF    40960
#define COUP_OFF   43520

// fused-route smem (bytes): votes 184320 + svs0/svs2/s1p/s2p 2560 +
// sred 10240 + ccs 23080 = 220200
#define RF_SMEM (HN*ROW*2 + 4*160*4 + 16*160*4 + 10*577*4)

// ---------------- helpers ----------------------------------------------------
typedef unsigned long long u64t;
__device__ __forceinline__ u64t pack2(float lo, float hi) {
    u64t r; asm("mov.b64 %0, {%1, %2};" : "=l"(r) : "f"(lo), "f"(hi)); return r;
}
__device__ __forceinline__ void unpack2(u64t v, float& lo, float& hi) {
    asm("mov.b64 {%0, %1}, %2;" : "=f"(lo), "=f"(hi) : "l"(v));
}
__device__ __forceinline__ u64t fma2(u64t a, u64t b, u64t c) {
    u64t r; asm("fma.rn.f32x2 %0, %1, %2, %3;" : "=l"(r) : "l"(a), "l"(b), "l"(c)); return r;
}
__device__ __forceinline__ void stcs_f32(float* p, float v) {
    asm volatile("st.global.cs.f32 [%0], %1;" :: "l"(p), "f"(v));
}
__device__ __forceinline__ void cp_async16(void* smem_dst, const void* gsrc) {
    unsigned s = (unsigned)__cvta_generic_to_shared(smem_dst);
    asm volatile("cp.async.cg.shared.global [%0], [%1], 16;\n" :: "r"(s), "l"(gsrc));
}
__device__ __forceinline__ void cp_commit() {
    asm volatile("cp.async.commit_group;\n");
}
template <int N>
__device__ __forceinline__ void cp_wait() {
    asm volatile("cp.async.wait_group %0;\n" :: "n"(N));
}
__device__ __forceinline__ float ld_peer_f32(const float* p, uint32_t peer_rank) {
    uint32_t a = (uint32_t)__cvta_generic_to_shared((void*)p);
    uint32_t r; float v;
    asm volatile("mapa.shared::cluster.u32 %0, %1, %2;" : "=r"(r) : "r"(a), "r"(peer_rank));
    asm volatile("ld.shared::cluster.f32 %0, [%1];" : "=f"(v) : "r"(r));
    return v;
}
#define CLUSTER_SYNC() do { \
    asm volatile("barrier.cluster.arrive.aligned;" ::: "memory"); \
    asm volatile("barrier.cluster.wait.aligned;" ::: "memory"); \
} while (0)

// squash over a 16-lane o-group (full-warp participation required)
__device__ __forceinline__ float squash16(float s) {
    float sq = s * s;
#pragma unroll
    for (int m = 1; m < 16; m <<= 1)
        sq += __shfl_xor_sync(0xFFFFFFFFu, sq, m, 16);
    float norm = sqrtf(sq + 1e-8f);
    return sq / (1.0f + sq) * (s / norm);
}

// ============================================================================
// init: zero the pass-0 accumulator (re-zeroed every graph replay)
// ============================================================================
__global__ void init_kernel() {
    int i = blockIdx.x * blockDim.x + threadIdx.x;
    if (i < NB * CO) g_s0[i] = 0.f;
}

// ============================================================================
// Kernel A (R8): votes GEMM, f32x2, fp16 out, fused pass-0 s0 accumulation.
// grid (4 bc, 72 ng): block = 16 n x 64 b, 320 threads.
// ============================================================================
__global__ __launch_bounds__(320, 2) void votes_kernel(
    const float* __restrict__ P, const float* __restrict__ W)
{
    const int bc  = blockIdx.x;
    const int ng  = blockIdx.y;
    const int t   = threadIdx.x;
    const int tco = t % 40;
    const int tb  = t / 40;
    const int co4 = tco * 4;
    const int b8  = tb * 8;

    __shared__ float wt[16][164];
    __shared__ float spt[16][66];

    u64t s0acc[16];
#pragma unroll
    for (int j = 0; j < 16; j++) s0acc[j] = 0ull;

    for (int g = 0; g < GN; g++) {
        const int n = ng * GN + g;

        __syncthreads();

        {
            const float4* Wn = (const float4*)(W + (size_t)n * (CO * 16));
#pragma unroll
            for (int r = 0; r < 2; r++) {
                int f = t + r * 320;
                float4 x = Wn[f];
                int co = f >> 2, i0 = (f & 3) * 4;
                wt[i0 + 0][co] = x.x; wt[i0 + 1][co] = x.y;
                wt[i0 + 2][co] = x.z; wt[i0 + 3][co] = x.w;
            }
        }
        if (t < 256) {
            int b = t >> 2, i0 = (t & 3) * 4;
            float4 x = *(const float4*)(P + ((size_t)(bc * 64 + b) * NN + n) * 16 + i0);
            spt[i0 + 0][b] = x.x; spt[i0 + 1][b] = x.y;
            spt[i0 + 2][b] = x.z; spt[i0 + 3][b] = x.w;
        }
        __syncthreads();

        u64t acc[16];
#pragma unroll
        for (int j = 0; j < 16; j++) acc[j] = 0ull;

#pragma unroll
        for (int i = 0; i < 16; i++) {
            float4 w4 = *(const float4*)&wt[i][co4];
            u64t p0 = *(const u64t*)&spt[i][b8 + 0];
            u64t p1 = *(const u64t*)&spt[i][b8 + 2];
            u64t p2 = *(const u64t*)&spt[i][b8 + 4];
            u64t p3 = *(const u64t*)&spt[i][b8 + 6];
            u64t ww;
            ww = pack2(w4.x, w4.x);
            acc[0]  = fma2(ww, p0, acc[0]);  acc[1]  = fma2(ww, p1, acc[1]);
            acc[2]  = fma2(ww, p2, acc[2]);  acc[3]  = fma2(ww, p3, acc[3]);
            ww = pack2(w4.y, w4.y);
            acc[4]  = fma2(ww, p0, acc[4]);  acc[5]  = fma2(ww, p1, acc[5]);
            acc[6]  = fma2(ww, p2, acc[6]);  acc[7]  = fma2(ww, p3, acc[7]);
            ww = pack2(w4.z, w4.z);
            acc[8]  = fma2(ww, p0, acc[8]);  acc[9]  = fma2(ww, p1, acc[9]);
            acc[10] = fma2(ww, p2, acc[10]); acc[11] = fma2(ww, p3, acc[11]);
            ww = pack2(w4.w, w4.w);
            acc[12] = fma2(ww, p0, acc[12]); acc[13] = fma2(ww, p1, acc[13]);
            acc[14] = fma2(ww, p2, acc[14]); acc[15] = fma2(ww, p3, acc[15]);
        }

#pragma unroll
        for (int k = 0; k < 4; k++) {
            float lo[4], hi[4];
#pragma unroll
            for (int j = 0; j < 4; j++) {
                u64t a = acc[j * 4 + k];
                s0acc[j * 4 + k] = fma2(pack2(1.f, 1.f), a, s0acc[j * 4 + k]);
                unpack2(a, lo[j], hi[j]);
            }
            union { __half2 h[2]; u64t u; } pk;
            pk.h[0] = __floats2half2_rn(lo[0], lo[1]);
            pk.h[1] = __floats2half2_rn(lo[2], lo[3]);
            *(u64t*)(g_votes + ((size_t)(bc * 64 + b8 + 2*k) * NN + n) * ROW + co4) = pk.u;
            pk.h[0] = __floats2half2_rn(hi[0], hi[1]);
            pk.h[1] = __floats2half2_rn(hi[2], hi[3]);
            *(u64t*)(g_votes + ((size_t)(bc * 64 + b8 + 2*k + 1) * NN + n) * ROW + co4) = pk.u;
        }
    }

#pragma unroll
    for (int k = 0; k < 4; k++) {
#pragma unroll
        for (int j = 0; j < 4; j++) {
            float lo, hi;
            unpack2(s0acc[j * 4 + k], lo, hi);
            atomicAdd(&g_s0[(bc * 64 + b8 + 2*k)     * CO + co4 + j], 0.1f * lo);
            atomicAdd(&g_s0[(bc * 64 + b8 + 2*k + 1) * CO + co4 + j], 0.1f * hi);
        }
    }
}

// ============================================================================
// Fused route: cluster of 2 CTAs = one batch b. Each CTA stages its 576-n
// half of votes[b] in smem (184KB) via cp.async, runs pass1 from smem,
// exchanges the 160-float partial s1 with the peer via DSMEM + cluster
// barrier, then runs pass2 entirely from smem and writes all outputs.
// 512 threads = 32 n-slots x 16 c-lanes.
// ============================================================================
__global__ __cluster_dims__(2, 1, 1) __launch_bounds__(512, 1)
void route_fused(const float* __restrict__ bias, float* __restrict__ out)
{
    extern __shared__ __align__(16) unsigned char smem[];
    __half* sv  = (__half*)smem;                       // 576*160 halves
    float* svs0 = (float*)(smem + HN * ROW * 2);       // v0            [160]
    float* svs2 = svs0 + 160;                          // v0+v1         [160]
    float* s1p  = svs2 + 160;                          // s1 partial    [160]
    float* s2p  = s1p + 160;                           // s2 partial    [160]
    float* sred = s2p + 160;                           // 16 warps x 160
    float* ccs  = sred + 16 * 160;                     // [10][577]

    const int b       = blockIdx.x >> 1;
    const uint32_t rk = blockIdx.x & 1;
    const int t  = threadIdx.x;
    const int nl = t >> 4;
    const int cl = t & 15;
    const int w  = t >> 5;
    const bool act = (cl < 10);

    // v0 = squash(s0 + bias)
    float bs_reg = 0.f;
    if (t < 160) {
        bs_reg = bias[t];
        svs0[t] = squash16(g_s0[b * CO + t] + bs_reg);
    }

    // stage this CTA's 576-n votes: 6 tiles x 96 n (1920 x 16B each)
    const __half* vb = g_votes + ((size_t)b * NN + (size_t)rk * HN) * ROW;
    for (int tile = 0; tile < 6; tile++) {
        const __half* src = vb + (size_t)tile * 96 * ROW;
        __half* dst = sv + tile * 96 * ROW;
#pragma unroll
        for (int i = 0; i < 4; i++) {
            int idx = t + i * 512;
            if (idx < 1920) cp_async16(dst + idx * 8, src + idx * 8);
        }
        cp_commit();
    }

    __syncthreads();   // svs0 visible

    __half2 vsh[8];
    {
        const float* src = svs0 + (act ? cl : 0) * 16;
#pragma unroll
        for (int j = 0; j < 8; j++)
            vsh[j] = __floats2half2_rn(src[2*j], src[2*j + 1]);
    }

    __half2 sacc[8];
#pragma unroll
    for (int j = 0; j < 8; j++) sacc[j] = __float2half2_rn(0.f);

    // ---------------- pass 1 (consume tiles as they land) ----------------
    for (int tile = 0; tile < 6; tile++) {
        switch (tile) {
            case 0: cp_wait<5>(); break;
            case 1: cp_wait<4>(); break;
            case 2: cp_wait<3>(); break;
            case 3: cp_wait<2>(); break;
            case 4: cp_wait<1>(); break;
            default: cp_wait<0>(); break;
        }
        __syncthreads();
#pragma unroll
        for (int kk = 0; kk < 3; kk++) {
            const int nloc = tile * 96 + kk * 32 + nl;
            const uint4* rp = (const uint4*)(sv + (size_t)nloc * ROW + (act ? cl : 0) * 16);
            uint4 q0 = rp[0];
            uint4 q1 = rp[1];
            __half2 vv[8];
            vv[0] = *(__half2*)&q0.x; vv[1] = *(__half2*)&q0.y;
            vv[2] = *(__half2*)&q0.z; vv[3] = *(__half2*)&q0.w;
            vv[4] = *(__half2*)&q1.x; vv[5] = *(__half2*)&q1.y;
            vv[6] = *(__half2*)&q1.z; vv[7] = *(__half2*)&q1.w;

            float lg = 0.f;
            if (act) {
                __half2 la = __hmul2(vv[0], vsh[0]);
                __half2 lb = __hmul2(vv[1], vsh[1]);
                la = __hfma2(vv[2], vsh[2], la);
                lb = __hfma2(vv[3], vsh[3], lb);
                la = __hfma2(vv[4], vsh[4], la);
                lb = __hfma2(vv[5], vsh[5], lb);
                la = __hfma2(vv[6], vsh[6], la);
                lb = __hfma2(vv[7], vsh[7], lb);
                float2 fa = __half22float2(la);
                float2 fb = __half22float2(lb);
                lg = (fa.x + fa.y) + (fb.x + fb.y);
            }
            float e = act ? __expf(lg) : 0.f;
            float den = e;
#pragma unroll
            for (int m = 1; m < 16; m <<= 1)
                den += __shfl_xor_sync(0xFFFFFFFFu, den, m, 16);
            float cc = __fdividef(e, den);
            if (act) {
                __half2 cch = __float2half2_rn(cc);
#pragma unroll
                for (int j = 0; j < 8; j++) sacc[j] = __hfma2(cch, vv[j], sacc[j]);
            }
        }
    }

    // fold warp's 2 n-slots, per-warp partials -> sred
    {
        float sf[16];
#pragma unroll
        for (int j = 0; j < 8; j++) {
            float2 f = __half22float2(sacc[j]);
            sf[2*j] = f.x; sf[2*j + 1] = f.y;
        }
#pragma unroll
        for (int o = 0; o < 16; o++)
            sf[o] += __shfl_xor_sync(0xFFFFFFFFu, sf[o], 16, 32);
        if ((t & 16) == 0 && act) {
            float* dst = sred + w * 160 + cl * 16;
#pragma unroll
            for (int j = 0; j < 4; j++)
                *(float4*)(dst + j * 4) =
                    make_float4(sf[j*4], sf[j*4+1], sf[j*4+2], sf[j*4+3]);
        }
    }
    __syncthreads();

    if (t < 160) {
        float s = 0.f;
#pragma unroll
        for (int w2 = 0; w2 < 16; w2++) s += sred[w2 * 160 + t];
        s1p[t] = s;
    }

    CLUSTER_SYNC();    // s1p of both CTAs complete & visible

    if (t < 160) {
        float peer = ld_peer_f32(&s1p[t], rk ^ 1u);
        float v1 = squash16(s1p[t] + peer + bs_reg);
        svs2[t] = svs0[t] + v1;
    }
    __syncthreads();

    // ---------------- pass 2 (all from smem) ----------------
    {
        const float* src = svs2 + (act ? cl : 0) * 16;
#pragma unroll
        for (int j = 0; j < 8; j++)
            vsh[j] = __floats2half2_rn(src[2*j], src[2*j + 1]);
    }
#pragma unroll
    for (int j = 0; j < 8; j++) sacc[j] = __float2half2_rn(0.f);

#pragma unroll 2
    for (int k = 0; k < 18; k++) {
        const int nloc = k * 32 + nl;
        const uint4* rp = (const uint4*)(sv + (size_t)nloc * ROW + (act ? cl : 0) * 16);
        uint4 q0 = rp[0];
        uint4 q1 = rp[1];
        __half2 vv[8];
        vv[0] = *(__half2*)&q0.x; vv[1] = *(__half2*)&q0.y;
        vv[2] = *(__half2*)&q0.z; vv[3] = *(__half2*)&q0.w;
        vv[4] = *(__half2*)&q1.x; vv[5] = *(__half2*)&q1.y;
        vv[6] = *(__half2*)&q1.z; vv[7] = *(__half2*)&q1.w;

        float lg = 0.f;
        if (act) {
            __half2 la = __hmul2(vv[0], vsh[0]);
            __half2 lb = __hmul2(vv[1], vsh[1]);
            la = __hfma2(vv[2], vsh[2], la);
            lb = __hfma2(vv[3], vsh[3], lb);
            la = __hfma2(vv[4], vsh[4], la);
            lb = __hfma2(vv[5], vsh[5], lb);
            la = __hfma2(vv[6], vsh[6], la);
            lb = __hfma2(vv[7], vsh[7], lb);
            float2 fa = __half22float2(la);
            float2 fb = __half22float2(lb);
            lg = (fa.x + fa.y) + (fb.x + fb.y);
        }
        float e = act ? __expf(lg) : 0.f;
        float den = e;
#pragma unroll
        for (int m = 1; m < 16; m <<= 1)
            den += __shfl_xor_sync(0xFFFFFFFFu, den, m, 16);
        float cc = __fdividef(e, den);
        if (act) {
            __half2 cch = __float2half2_rn(cc);
#pragma unroll
            for (int j = 0; j < 8; j++) sacc[j] = __hfma2(cch, vv[j], sacc[j]);
            ccs[cl * 577 + nloc] = cc;
        }
    }

    {
        float sf[16];
#pragma unroll
        for (int j = 0; j < 8; j++) {
            float2 f = __half22float2(sacc[j]);
            sf[2*j] = f.x; sf[2*j + 1] = f.y;
        }
#pragma unroll
        for (int o = 0; o < 16; o++)
            sf[o] += __shfl_xor_sync(0xFFFFFFFFu, sf[o], 16, 32);
        if ((t & 16) == 0 && act) {
            float* dst = sred + w * 160 + cl * 16;
#pragma unroll
            for (int j = 0; j < 4; j++)
                *(float4*)(dst + j * 4) =
                    make_float4(sf[j*4], sf[j*4+1], sf[j*4+2], sf[j*4+3]);
        }
    }
    __syncthreads();

    if (t < 160) {
        float s = 0.f;
#pragma unroll
        for (int w2 = 0; w2 < 16; w2++) s += sred[w2 * 160 + t];
        s2p[t] = s;
    }

    CLUSTER_SYNC();    // s2p of both CTAs complete & visible

    if (t < 160) {
        float peer = ld_peer_f32(&s2p[t], rk ^ 1u);
        float v = squash16(s2p[t] + peer + bs_reg);
        float vsq = v * v;
#pragma unroll
        for (int m = 1; m < 16; m <<= 1)
            vsq += __shfl_xor_sync(0xFFFFFFFFu, vsq, m, 16);
        if (rk == 0) {
            stcs_f32(out + POSE_OFF + (size_t)b * CO + t, v);
            if ((t & 15) == 0)
                stcs_f32(out + ACT_OFF + b * NC + (t >> 4), sqrtf(vsq + 1e-8f));
        }
    }

    // coupling: out[b][c][n], this CTA's n-half, coalesced from ccs
    for (int idx = t; idx < NC * HN; idx += 512) {
        int c = idx / HN, nn = idx % HN;
        stcs_f32(out + COUP_OFF + (size_t)b * (NC * NN) + (size_t)c * NN
                 + (size_t)rk * HN + nn, ccs[c * 577 + nn]);
    }

    CLUSTER_SYNC();    // no CTA exits while peer may still DSMEM-read
}

// ============================================================================
extern "C" void kernel_launch(void* const* d_in, const int* in_sizes, int n_in,
                              void* d_out, int out_size)
{
    const float* P    = (const float*)d_in[0];  // (256,32,6,6,16,1)
    const float* W    = (const float*)d_in[2];  // (32,6,6,10,16,16)
    const float* bias = (const float*)d_in[3];  // (10,1,1,16,1)
    float* out = (float*)d_out;

    cudaFuncSetAttribute(route_fused,
                         cudaFuncAttributeMaxDynamicSharedMemorySize, RF_SMEM);

    init_kernel<<<(NB * CO + 511) / 512, 512>>>();
    votes_kernel<<<dim3(4, NGRP), 320>>>(P, W);
    route_fused<<<2 * NB, 512, RF_SMEM>>>(bias, out);
}